// round 3
// baseline (speedup 1.0000x reference)
#include <cuda_runtime.h>

#define NG 512   // total groups (4 * 4096/32)
#define TG 32    // tokens per group
#define DD 1024  // model dim
#define NE 32    // experts
#define NS 128   // expert hidden size

__device__ float g_w[NG * NE];
__device__ int   g_sel[NG * NE];
__device__ float g_inner[(size_t)NE * NG * NS];  // 8 MB scratch

// ---- packed f32x2 helpers (FFMA2 only reachable via PTX) ----
static __device__ __forceinline__ unsigned long long pack2(float lo, float hi) {
    unsigned long long r;
    asm("mov.b64 %0, {%1, %2};" : "=l"(r) : "f"(lo), "f"(hi));
    return r;
}
static __device__ __forceinline__ void fma2(unsigned long long &d,
                                            unsigned long long a,
                                            unsigned long long b) {
    asm("fma.rn.f32x2 %0, %1, %2, %0;" : "+l"(d) : "l"(a), "l"(b));
}
static __device__ __forceinline__ float2 unpack2(unsigned long long v) {
    float lo, hi;
    asm("mov.b64 {%0, %1}, %2;" : "=f"(lo), "=f"(hi) : "l"(v));
    return make_float2(lo, hi);
}

// ---------------------------------------------------------------------------
// Router: 64 tokens x 32 experts per CTA, 128 threads, 4x4 micro in f32x2.
// Also zero-fills its slice of `out` (fire-and-forget stores) so no memset
// kernel is needed before gemm2's red.global.add.
// ---------------------------------------------------------------------------
#define RT 64    // tokens per block (2 groups)
#define RDC 64   // d-chunk
#define XPAD 68  // xs row stride

__global__ __launch_bounds__(128) void router_kernel(
    const float* __restrict__ x, const float* __restrict__ ctrl,
    float* __restrict__ out, int out_n4)
{
    __shared__ __align__(16) float xs[RT * XPAD];  // aliased as Ls later
    __shared__ __align__(16) float cs[RDC][NE];
    int tid = threadIdx.x;
    int tokbase = blockIdx.x * RT;

    // ---- zero-fill out slice (stores drain while we compute) ----
    {
        float4 z = make_float4(0.f, 0.f, 0.f, 0.f);
        for (int i = blockIdx.x * 128 + tid; i < out_n4; i += gridDim.x * 128)
            ((float4*)out)[i] = z;
    }

    int mt = (tid >> 3) << 2;   // token offset 0..60
    int et = (tid & 7) << 2;    // expert offset 0..28

    unsigned long long acc[4][2];
#pragma unroll
    for (int i = 0; i < 4; i++) { acc[i][0] = 0ULL; acc[i][1] = 0ULL; }

    for (int dc = 0; dc < DD; dc += RDC) {
        __syncthreads();
        // x chunk: 64 tokens x 64 d
#pragma unroll
        for (int it = 0; it < 8; it++) {
            int t  = (tid >> 4) + (it << 3);
            int d4 = (tid & 15) << 2;
            *(float4*)&xs[t * XPAD + d4] =
                *(const float4*)(x + (size_t)(tokbase + t) * DD + dc + d4);
        }
        // ctrl chunk: 64 d x 32 e
#pragma unroll
        for (int it = 0; it < 4; it++) {
            int q  = tid + (it << 7);       // float4 slot 0..511
            int d  = q >> 3;
            int e4 = (q & 7) << 2;
            *(float4*)&cs[d][e4] = *(const float4*)(ctrl + (size_t)(dc + d) * NE + e4);
        }
        __syncthreads();
#pragma unroll 4
        for (int d = 0; d < RDC; d += 4) {
            float4 xr[4];
#pragma unroll
            for (int i = 0; i < 4; i++)
                xr[i] = *(const float4*)&xs[(mt + i) * XPAD + d];
#pragma unroll
            for (int dd = 0; dd < 4; dd++) {
                ulonglong2 cb = *(const ulonglong2*)&cs[d + dd][et];
                float xv[4];
                xv[0] = (dd == 0) ? xr[0].x : (dd == 1) ? xr[0].y : (dd == 2) ? xr[0].z : xr[0].w;
                xv[1] = (dd == 0) ? xr[1].x : (dd == 1) ? xr[1].y : (dd == 2) ? xr[1].z : xr[1].w;
                xv[2] = (dd == 0) ? xr[2].x : (dd == 1) ? xr[2].y : (dd == 2) ? xr[2].z : xr[2].w;
                xv[3] = (dd == 0) ? xr[3].x : (dd == 1) ? xr[3].y : (dd == 2) ? xr[3].z : xr[3].w;
#pragma unroll
                for (int i = 0; i < 4; i++) {
                    unsigned long long ad = pack2(xv[i], xv[i]);
                    fma2(acc[i][0], ad, cb.x);
                    fma2(acc[i][1], ad, cb.y);
                }
            }
        }
    }
    __syncthreads();

    // logits (+tie-break) into aliased smem
    float* Ls = xs;                        // 64*32 floats
    const float step = 1e-6f / 31.0f;
#pragma unroll
    for (int i = 0; i < 4; i++) {
        int t = mt + i;
        float tb = (float)(t & 31) * step;
        float2 v0 = unpack2(acc[i][0]);
        float2 v1 = unpack2(acc[i][1]);
        Ls[t * NE + et + 0] = v0.x + tb;
        Ls[t * NE + et + 1] = v0.y + tb;
        Ls[t * NE + et + 2] = v1.x + tb;
        Ls[t * NE + et + 3] = v1.y + tb;
    }
    __syncthreads();

    if (tid < 64) {
        int gq = tid >> 5;
        int e  = tid & 31;
        int g  = blockIdx.x * 2 + gq;
        float m = Ls[(gq * TG) * NE + e];
        int am = 0;
#pragma unroll
        for (int t = 1; t < TG; t++) {
            float v = Ls[(gq * TG + t) * NE + e];
            if (v > m) { m = v; am = t; }
        }
        float s = 0.f;
#pragma unroll
        for (int t = 0; t < TG; t++) s += __expf(Ls[(gq * TG + t) * NE + e] - m);
        g_w[g * NE + e]   = 1.0f / s;
        g_sel[g * NE + e] = am;
    }
}

// ---------------------------------------------------------------------------
// FF1: INNER = relu( (w * x[sel]) @ f1[:,e,:] + f1b[e,:] )
// Batched GEMM M=512 K=1024 N=128. Tile 64x128, BK=16, 128 thr, 8x8 micro,
// double-buffered smem. Grid (8, 32) = 256 CTAs.
// ---------------------------------------------------------------------------
__global__ __launch_bounds__(128) void gemm1_kernel(
    const float* __restrict__ x, const float* __restrict__ f1,
    const float* __restrict__ f1b)
{
    const int BK = 16;
    __shared__ __align__(16) float As[2][BK][64];
    __shared__ __align__(16) float Bs[2][BK][128];
    int e     = blockIdx.y;
    int gbase = blockIdx.x * 64;
    int tid   = threadIdx.x;

    // A loader: 64 rows x 16 k, each thread 8 floats (2x float4)
    int lm = tid & 63;
    int kh = (tid >> 6) << 3;        // 0 or 8
    int gg = gbase + lm;
    float wv = g_w[gg * NE + e];
    const float* arow = x + (size_t)(gg * TG + g_sel[gg * NE + e]) * DD;

    // B loader: f1[k, e, n] (row stride NE*NS); 16 k-rows, each thread 16 floats
    int bk = tid >> 3;               // 0..15
    int bn = (tid & 7) << 4;         // 0,16,...,112
    const float* bcol = f1 + (size_t)e * NS + bn;

    unsigned long long acc[8][4];
#pragma unroll
    for (int i = 0; i < 8; i++)
#pragma unroll
        for (int j = 0; j < 4; j++) acc[i][j] = 0ULL;

    int mt = (tid >> 4) << 3;        // 0..56
    int nt = (tid & 15) << 3;        // 0..120

    // preload tile 0
    float4 pa0 = *(const float4*)(arow + kh);
    float4 pa1 = *(const float4*)(arow + kh + 4);
    float4 pb0 = *(const float4*)(bcol + (size_t)bk * (NE * NS));
    float4 pb1 = *(const float4*)(bcol + (size_t)bk * (NE * NS) + 4);
    float4 pb2 = *(const float4*)(bcol + (size_t)bk * (NE * NS) + 8);
    float4 pb3 = *(const float4*)(bcol + (size_t)bk * (NE * NS) + 12);
    As[0][kh + 0][lm] = pa0.x * wv; As[0][kh + 1][lm] = pa0.y * wv;
    As[0][kh + 2][lm] = pa0.z * wv; As[0][kh + 3][lm] = pa0.w * wv;
    As[0][kh + 4][lm] = pa1.x * wv; As[0][kh + 5][lm] = pa1.y * wv;
    As[0][kh + 6][lm] = pa1.z * wv; As[0][kh + 7][lm] = pa1.w * wv;
    *(float4*)&Bs[0][bk][bn]      = pb0;
    *(float4*)&Bs[0][bk][bn + 4]  = pb1;
    *(float4*)&Bs[0][bk][bn + 8]  = pb2;
    *(float4*)&Bs[0][bk][bn + 12] = pb3;
    __syncthreads();

    int cur = 0;
    for (int kt = 0; kt < DD; kt += BK) {
        bool more = (kt + BK < DD);
        if (more) {
            pa0 = *(const float4*)(arow + kt + BK + kh);
            pa1 = *(const float4*)(arow + kt + BK + kh + 4);
            const float* bp = bcol + (size_t)(kt + BK + bk) * (NE * NS);
            pb0 = *(const float4*)(bp);
            pb1 = *(const float4*)(bp + 4);
            pb2 = *(const float4*)(bp + 8);
            pb3 = *(const float4*)(bp + 12);
        }
#pragma unroll
        for (int k = 0; k < BK; k++) {
            float4 a0 = *(const float4*)&As[cur][k][mt];
            float4 a1 = *(const float4*)&As[cur][k][mt + 4];
            ulonglong2 b0 = *(const ulonglong2*)&Bs[cur][k][nt];
            ulonglong2 b1 = *(const ulonglong2*)&Bs[cur][k][nt + 4];
            float av[8] = {a0.x, a0.y, a0.z, a0.w, a1.x, a1.y, a1.z, a1.w};
#pragma unroll
            for (int i = 0; i < 8; i++) {
                unsigned long long ad = pack2(av[i], av[i]);
                fma2(acc[i][0], ad, b0.x);
                fma2(acc[i][1], ad, b0.y);
                fma2(acc[i][2], ad, b1.x);
                fma2(acc[i][3], ad, b1.y);
            }
        }
        if (more) {
            int nxt = cur ^ 1;
            As[nxt][kh + 0][lm] = pa0.x * wv; As[nxt][kh + 1][lm] = pa0.y * wv;
            As[nxt][kh + 2][lm] = pa0.z * wv; As[nxt][kh + 3][lm] = pa0.w * wv;
            As[nxt][kh + 4][lm] = pa1.x * wv; As[nxt][kh + 5][lm] = pa1.y * wv;
            As[nxt][kh + 6][lm] = pa1.z * wv; As[nxt][kh + 7][lm] = pa1.w * wv;
            *(float4*)&Bs[nxt][bk][bn]      = pb0;
            *(float4*)&Bs[nxt][bk][bn + 4]  = pb1;
            *(float4*)&Bs[nxt][bk][bn + 8]  = pb2;
            *(float4*)&Bs[nxt][bk][bn + 12] = pb3;
            cur = nxt;
            __syncthreads();
        }
    }

    float bias[8];
#pragma unroll
    for (int j = 0; j < 8; j++) bias[j] = f1b[e * NS + nt + j];
    float* obase = g_inner + ((size_t)e * NG + gbase) * NS;
#pragma unroll
    for (int i = 0; i < 8; i++) {
        float o[8];
#pragma unroll
        for (int j = 0; j < 4; j++) {
            float2 v = unpack2(acc[i][j]);
            o[2 * j]     = fmaxf(v.x + bias[2 * j],     0.f);
            o[2 * j + 1] = fmaxf(v.y + bias[2 * j + 1], 0.f);
        }
        size_t off = (size_t)(mt + i) * NS + nt;
        *(float4*)&obase[off]     = make_float4(o[0], o[1], o[2], o[3]);
        *(float4*)&obase[off + 4] = make_float4(o[4], o[5], o[6], o[7]);
    }
}

// ---------------------------------------------------------------------------
// FF2 + combine: Y = INNER[e] @ f2[e]; out[token(g,e),:] += w*Y via red.v4
// Batched GEMM M=512 K=128 N=1024. Tile 128x128, BK=16, 256 thr, 8x8 micro,
// double-buffered. Grid (4, 8, 32) = 1024 CTAs.
// ---------------------------------------------------------------------------
__global__ __launch_bounds__(256) void gemm2_kernel(
    const float* __restrict__ f2, float* __restrict__ out)
{
    const int BK = 16;
    __shared__ __align__(16) float As[2][BK][128];
    __shared__ __align__(16) float Bs[2][BK][128];
    int e     = blockIdx.z;
    int gbase = blockIdx.x * 128;
    int nbase = blockIdx.y * 128;
    int tid   = threadIdx.x;

    int lm = tid & 127;
    int kh = (tid >> 7) << 3;        // 0 or 8
    const float* arow = g_inner + ((size_t)e * NG + gbase + lm) * NS;

    int bk = tid >> 4;               // 0..15
    int bn = (tid & 15) << 3;        // 0..120
    const float* bbase = f2 + (size_t)e * NS * DD + nbase + bn;

    unsigned long long acc[8][4];
#pragma unroll
    for (int i = 0; i < 8; i++)
#pragma unroll
        for (int j = 0; j < 4; j++) acc[i][j] = 0ULL;

    int mt = (tid >> 4) << 3;
    int nt = (tid & 15) << 3;

    float4 pa0 = *(const float4*)(arow + kh);
    float4 pa1 = *(const float4*)(arow + kh + 4);
    float4 pb0 = *(const float4*)(bbase + (size_t)bk * DD);
    float4 pb1 = *(const float4*)(bbase + (size_t)bk * DD + 4);
    As[0][kh + 0][lm] = pa0.x; As[0][kh + 1][lm] = pa0.y;
    As[0][kh + 2][lm] = pa0.z; As[0][kh + 3][lm] = pa0.w;
    As[0][kh + 4][lm] = pa1.x; As[0][kh + 5][lm] = pa1.y;
    As[0][kh + 6][lm] = pa1.z; As[0][kh + 7][lm] = pa1.w;
    *(float4*)&Bs[0][bk][bn]     = pb0;
    *(float4*)&Bs[0][bk][bn + 4] = pb1;
    __syncthreads();

    int cur = 0;
    for (int kt = 0; kt < NS; kt += BK) {
        bool more = (kt + BK < NS);
        if (more) {
            pa0 = *(const float4*)(arow + kt + BK + kh);
            pa1 = *(const float4*)(arow + kt + BK + kh + 4);
            pb0 = *(const float4*)(bbase + (size_t)(kt + BK + bk) * DD);
            pb1 = *(const float4*)(bbase + (size_t)(kt + BK + bk) * DD + 4);
        }
#pragma unroll
        for (int k = 0; k < BK; k++) {
            float4 a0 = *(const float4*)&As[cur][k][mt];
            float4 a1 = *(const float4*)&As[cur][k][mt + 4];
            ulonglong2 b0 = *(const ulonglong2*)&Bs[cur][k][nt];
            ulonglong2 b1 = *(const ulonglong2*)&Bs[cur][k][nt + 4];
            float av[8] = {a0.x, a0.y, a0.z, a0.w, a1.x, a1.y, a1.z, a1.w};
#pragma unroll
            for (int i = 0; i < 8; i++) {
                unsigned long long ad = pack2(av[i], av[i]);
                fma2(acc[i][0], ad, b0.x);
                fma2(acc[i][1], ad, b0.y);
                fma2(acc[i][2], ad, b1.x);
                fma2(acc[i][3], ad, b1.y);
            }
        }
        if (more) {
            int nxt = cur ^ 1;
            As[nxt][kh + 0][lm] = pa0.x; As[nxt][kh + 1][lm] = pa0.y;
            As[nxt][kh + 2][lm] = pa0.z; As[nxt][kh + 3][lm] = pa0.w;
            As[nxt][kh + 4][lm] = pa1.x; As[nxt][kh + 5][lm] = pa1.y;
            As[nxt][kh + 6][lm] = pa1.z; As[nxt][kh + 7][lm] = pa1.w;
            *(float4*)&Bs[nxt][bk][bn]     = pb0;
            *(float4*)&Bs[nxt][bk][bn + 4] = pb1;
            cur = nxt;
            __syncthreads();
        }
    }

#pragma unroll
    for (int i = 0; i < 8; i++) {
        int gg  = gbase + mt + i;
        int tok = gg * TG + g_sel[gg * NE + e];
        float wv = g_w[gg * NE + e];
        float* orow = out + (size_t)tok * DD + nbase + nt;
        float2 v0 = unpack2(acc[i][0]);
        float2 v1 = unpack2(acc[i][1]);
        float2 v2 = unpack2(acc[i][2]);
        float2 v3 = unpack2(acc[i][3]);
        asm volatile("red.global.add.v4.f32 [%0], {%1, %2, %3, %4};"
                     :: "l"(orow), "f"(wv * v0.x), "f"(wv * v0.y),
                        "f"(wv * v1.x), "f"(wv * v1.y) : "memory");
        asm volatile("red.global.add.v4.f32 [%0], {%1, %2, %3, %4};"
                     :: "l"(orow + 4), "f"(wv * v2.x), "f"(wv * v2.y),
                        "f"(wv * v3.x), "f"(wv * v3.y) : "memory");
    }
}

// ---------------------------------------------------------------------------
extern "C" void kernel_launch(void* const* d_in, const int* in_sizes, int n_in,
                              void* d_out, int out_size) {
    const float* x    = (const float*)d_in[0];
    const float* ctrl = (const float*)d_in[1];
    const float* f1   = (const float*)d_in[2];
    const float* f2   = (const float*)d_in[3];
    const float* f1b  = (const float*)d_in[4];
    float* out = (float*)d_out;

    router_kernel<<<NG * TG / RT, 128>>>(x, ctrl, out, out_size / 4);
    gemm1_kernel<<<dim3(NG / 64, NE), 128>>>(x, f1, f1b);
    gemm2_kernel<<<dim3(NG / 128, DD / 128, NE), 256>>>(f2, out);
}

// round 5
// speedup vs baseline: 1.5283x; 1.5283x over previous
#include <cuda_runtime.h>
#include <cuda_bf16.h>
#include <cstdint>

#define NG 512   // total groups
#define TG 32    // tokens per group
#define DD 1024  // model dim
#define NE 32    // experts
#define NS 128   // expert hidden size

__device__ float g_w[NG * NE];
__device__ int   g_sel[NG * NE];
// pre-transposed + bf16-split weights: B1[e][n][k], B2[e][d][s]
__device__ __nv_bfloat16 g_B1hi[(size_t)NE * NS * DD];
__device__ __nv_bfloat16 g_B1lo[(size_t)NE * NS * DD];
__device__ __nv_bfloat16 g_B2hi[(size_t)NE * DD * NS];
__device__ __nv_bfloat16 g_B2lo[(size_t)NE * DD * NS];
// inner activations, bf16-split: I[e][g][s]
__device__ __nv_bfloat16 g_Ihi[(size_t)NE * NG * NS];
__device__ __nv_bfloat16 g_Ilo[(size_t)NE * NG * NS];

// ============================ helpers ============================
static __device__ __forceinline__ uint32_t smem_to_u32(const void* p) {
    uint32_t a;
    asm("{ .reg .u64 t; cvta.to.shared.u64 t, %1; cvt.u32.u64 %0, t; }"
        : "=r"(a) : "l"(p));
    return a;
}
static __device__ __forceinline__ void ldmat_x4(
    uint32_t& r0, uint32_t& r1, uint32_t& r2, uint32_t& r3, uint32_t addr)
{
    asm volatile("ldmatrix.sync.aligned.m8n8.x4.shared.b16 {%0,%1,%2,%3}, [%4];"
                 : "=r"(r0), "=r"(r1), "=r"(r2), "=r"(r3) : "r"(addr));
}
static __device__ __forceinline__ void mma16816(
    float* d, uint32_t a0, uint32_t a1, uint32_t a2, uint32_t a3,
    uint32_t b0, uint32_t b1)
{
    asm volatile("mma.sync.aligned.m16n8k16.row.col.f32.bf16.bf16.f32 "
                 "{%0,%1,%2,%3}, {%4,%5,%6,%7}, {%8,%9}, {%0,%1,%2,%3};"
                 : "+f"(d[0]), "+f"(d[1]), "+f"(d[2]), "+f"(d[3])
                 : "r"(a0), "r"(a1), "r"(a2), "r"(a3), "r"(b0), "r"(b1));
}
// ---- packed f32x2 helpers (router) ----
static __device__ __forceinline__ unsigned long long pack2(float lo, float hi) {
    unsigned long long r;
    asm("mov.b64 %0, {%1, %2};" : "=l"(r) : "f"(lo), "f"(hi));
    return r;
}
static __device__ __forceinline__ void fma2(unsigned long long &d,
                                            unsigned long long a, unsigned long long b) {
    asm("fma.rn.f32x2 %0, %1, %2, %0;" : "+l"(d) : "l"(a), "l"(b));
}
static __device__ __forceinline__ float2 unpack2(unsigned long long v) {
    float lo, hi;
    asm("mov.b64 {%0, %1}, %2;" : "=f"(lo), "=f"(hi) : "l"(v));
    return make_float2(lo, hi);
}
static __device__ __forceinline__ void split_bf16(float v, __nv_bfloat16& h, __nv_bfloat16& l) {
    h = __float2bfloat16_rn(v);
    l = __float2bfloat16_rn(v - __bfloat162float(h));
}
static __device__ __forceinline__ uint32_t packbf(__nv_bfloat16 a, __nv_bfloat16 b) {
    __nv_bfloat162 p = __halves2bfloat162(a, b);
    return *(uint32_t*)&p;
}

// ---------------------------------------------------------------------------
// Router: 128 tokens x 32 experts per CTA, 4x4 micro f32x2.
// ---------------------------------------------------------------------------
#define RT 128
#define RDC 64
#define XPAD 68

__global__ __launch_bounds__(256) void router_kernel(
    const float* __restrict__ x, const float* __restrict__ ctrl)
{
    __shared__ __align__(16) float xs[RT * XPAD];
    __shared__ __align__(16) float cs[RDC][NE];
    int tid = threadIdx.x;
    int tokbase = blockIdx.x * RT;

    int mt = (tid >> 3) << 2;
    int et = (tid & 7) << 2;

    unsigned long long acc[4][2];
#pragma unroll
    for (int i = 0; i < 4; i++) { acc[i][0] = 0ULL; acc[i][1] = 0ULL; }

    for (int dc = 0; dc < DD; dc += RDC) {
        __syncthreads();
#pragma unroll
        for (int it = 0; it < 8; it++) {
            int t  = (tid >> 4) + (it << 4);
            int d4 = (tid & 15) << 2;
            *(float4*)&xs[t * XPAD + d4] =
                *(const float4*)(x + (size_t)(tokbase + t) * DD + dc + d4);
        }
#pragma unroll
        for (int it = 0; it < 2; it++) {
            int q  = tid + (it << 8);
            int d  = q >> 3;
            int e4 = (q & 7) << 2;
            *(float4*)&cs[d][e4] = *(const float4*)(ctrl + (size_t)(dc + d) * NE + e4);
        }
        __syncthreads();
#pragma unroll 4
        for (int d = 0; d < RDC; d += 4) {
            float4 xr[4];
#pragma unroll
            for (int i = 0; i < 4; i++)
                xr[i] = *(const float4*)&xs[(mt + i) * XPAD + d];
#pragma unroll
            for (int dd = 0; dd < 4; dd++) {
                ulonglong2 cb = *(const ulonglong2*)&cs[d + dd][et];
                float xv[4];
                xv[0] = (dd == 0) ? xr[0].x : (dd == 1) ? xr[0].y : (dd == 2) ? xr[0].z : xr[0].w;
                xv[1] = (dd == 0) ? xr[1].x : (dd == 1) ? xr[1].y : (dd == 2) ? xr[1].z : xr[1].w;
                xv[2] = (dd == 0) ? xr[2].x : (dd == 1) ? xr[2].y : (dd == 2) ? xr[2].z : xr[2].w;
                xv[3] = (dd == 0) ? xr[3].x : (dd == 1) ? xr[3].y : (dd == 2) ? xr[3].z : xr[3].w;
#pragma unroll
                for (int i = 0; i < 4; i++) {
                    unsigned long long ad = pack2(xv[i], xv[i]);
                    fma2(acc[i][0], ad, cb.x);
                    fma2(acc[i][1], ad, cb.y);
                }
            }
        }
    }
    __syncthreads();

    float* Ls = xs;
    const float step = 1e-6f / 31.0f;
#pragma unroll
    for (int i = 0; i < 4; i++) {
        int t = mt + i;
        float tb = (float)(t & 31) * step;
        float2 v0 = unpack2(acc[i][0]);
        float2 v1 = unpack2(acc[i][1]);
        Ls[t * NE + et + 0] = v0.x + tb;
        Ls[t * NE + et + 1] = v0.y + tb;
        Ls[t * NE + et + 2] = v1.x + tb;
        Ls[t * NE + et + 3] = v1.y + tb;
    }
    __syncthreads();

    if (tid < 128) {
        int gq = tid >> 5;
        int e  = tid & 31;
        int g  = blockIdx.x * 4 + gq;
        float m = Ls[(gq * TG) * NE + e];
        int am = 0;
#pragma unroll
        for (int t = 1; t < TG; t++) {
            float v = Ls[(gq * TG + t) * NE + e];
            if (v > m) { m = v; am = t; }
        }
        float s = 0.f;
#pragma unroll
        for (int t = 0; t < TG; t++) s += __expf(Ls[(gq * TG + t) * NE + e] - m);
        g_w[g * NE + e]   = 1.0f / s;
        g_sel[g * NE + e] = am;
    }
}

// ---------------------------------------------------------------------------
// Weight transpose + bf16 split.
// f1[k][e][n] -> B1[e][n][k];  f2[e][s][d] -> B2[e][d][s]
// ---------------------------------------------------------------------------
__global__ __launch_bounds__(256) void transpose_f1_kernel(const float* __restrict__ f1)
{
    __shared__ float tile[32][33];
    int e  = blockIdx.z, nt = blockIdx.y, kt = blockIdx.x;
    int tx = threadIdx.x, ty = threadIdx.y;  // 32 x 8
#pragma unroll
    for (int r = 0; r < 4; r++) {
        int k = kt * 32 + ty + r * 8;
        tile[ty + r * 8][tx] = f1[((size_t)k * NE + e) * NS + nt * 32 + tx];
    }
    __syncthreads();
#pragma unroll
    for (int r = 0; r < 4; r++) {
        int n = nt * 32 + ty + r * 8;
        int k = kt * 32 + tx;
        float v = tile[tx][ty + r * 8];
        __nv_bfloat16 h, l;
        split_bf16(v, h, l);
        size_t idx = ((size_t)e * NS + n) * DD + k;
        g_B1hi[idx] = h;
        g_B1lo[idx] = l;
    }
}

__global__ __launch_bounds__(256) void transpose_f2_kernel(const float* __restrict__ f2)
{
    __shared__ float tile[32][33];
    int e  = blockIdx.z, st = blockIdx.y, dt = blockIdx.x;
    int tx = threadIdx.x, ty = threadIdx.y;
#pragma unroll
    for (int r = 0; r < 4; r++) {
        int s = st * 32 + ty + r * 8;
        tile[ty + r * 8][tx] = f2[((size_t)e * NS + s) * DD + dt * 32 + tx];
    }
    __syncthreads();
#pragma unroll
    for (int r = 0; r < 4; r++) {
        int d = dt * 32 + ty + r * 8;
        int s = st * 32 + tx;
        float v = tile[tx][ty + r * 8];
        __nv_bfloat16 h, l;
        split_bf16(v, h, l);
        size_t idx = ((size_t)e * DD + d) * NS + s;
        g_B2hi[idx] = h;
        g_B2lo[idx] = l;
    }
}

// ---------------------------------------------------------------------------
// FF1: D[64g,128s] = sum_k (w*x[sel])[64,k] x B1[128,k]^T, bf16 3-term split.
// 256 threads, warp grid 2x4, warp tile 32x32, BK=32, double-buffered smem.
// Row stride 80B (conflict-free ldmatrix).
// ---------------------------------------------------------------------------
#define RS 80
// per-buffer offsets (ff1): Ahi 64*80=5120, Alo 5120, Bhi 10240, Blo 10240
#define F1_AH 0
#define F1_AL 5120
#define F1_BH 10240
#define F1_BL 20480
#define F1_BUF 30720
#define F1_SMEM (2 * F1_BUF)

__global__ __launch_bounds__(256) void ff1_mma_kernel(
    const float* __restrict__ x, const float* __restrict__ f1b)
{
    extern __shared__ __align__(16) char smc[];
    uint32_t smu = smem_to_u32(smc);
    int tid  = threadIdx.x;
    int lane = tid & 31;
    int wid  = tid >> 5;
    int wm   = wid >> 2;     // 0..1
    int wn   = wid & 3;      // 0..3
    int e     = blockIdx.y;
    int gbase = blockIdx.x * 64;

    // A loader: row = tid/4 (0..63), chunks (tid%4)*2 + {0,1} of 4 fp32
    int ar  = tid >> 2;
    int ac0 = (tid & 3) << 1;
    int gg  = gbase + ar;
    float wv = g_w[gg * NE + e];
    const float* arow = x + (size_t)(gg * TG + g_sel[gg * NE + e]) * DD;

    // B loader: row = tid/2 (0..127), chunks (tid%2)*2 + {0,1} of 8 bf16
    int br  = tid >> 1;
    int bc0 = (tid & 1) << 1;
    const __nv_bfloat16* bhrow = g_B1hi + ((size_t)e * NS + br) * DD;
    const __nv_bfloat16* blrow = g_B1lo + ((size_t)e * NS + br) * DD;

    float acc[2][4][4];
#pragma unroll
    for (int i = 0; i < 2; i++)
#pragma unroll
        for (int j = 0; j < 4; j++)
#pragma unroll
            for (int q = 0; q < 4; q++) acc[i][j][q] = 0.f;

    float4 pa[2];
    uint4  pbh[2], pbl[2];

#define FF1_FETCH(kt) do {                                                   \
        pa[0]  = *(const float4*)(arow + (kt) + ac0 * 4);                    \
        pa[1]  = *(const float4*)(arow + (kt) + ac0 * 4 + 4);                \
        pbh[0] = *(const uint4*)(bhrow + (kt) + bc0 * 8);                    \
        pbh[1] = *(const uint4*)(bhrow + (kt) + bc0 * 8 + 8);                \
        pbl[0] = *(const uint4*)(blrow + (kt) + bc0 * 8);                    \
        pbl[1] = *(const uint4*)(blrow + (kt) + bc0 * 8 + 8);                \
    } while (0)

#define FF1_STORE(b) do {                                                    \
        char* bb = smc + (b) * F1_BUF;                                       \
        _Pragma("unroll")                                                    \
        for (int j = 0; j < 2; j++) {                                        \
            float4 v = pa[j];                                                \
            v.x *= wv; v.y *= wv; v.z *= wv; v.w *= wv;                      \
            __nv_bfloat16 h0,l0,h1,l1,h2,l2,h3,l3;                           \
            split_bf16(v.x,h0,l0); split_bf16(v.y,h1,l1);                    \
            split_bf16(v.z,h2,l2); split_bf16(v.w,h3,l3);                    \
            int off = ar * RS + (ac0 + j) * 8;                               \
            *(uint2*)(bb + F1_AH + off) = make_uint2(packbf(h0,h1), packbf(h2,h3)); \
            *(uint2*)(bb + F1_AL + off) = make_uint2(packbf(l0,l1), packbf(l2,l3)); \
        }                                                                    \
        _Pragma("unroll")                                                    \
        for (int j = 0; j < 2; j++) {                                        \
            int off = br * RS + (bc0 + j) * 16;                              \
            *(uint4*)(bb + F1_BH + off) = pbh[j];                            \
            *(uint4*)(bb + F1_BL + off) = pbl[j];                            \
        }                                                                    \
    } while (0)

    FF1_FETCH(0);
    FF1_STORE(0);
    __syncthreads();

    int cur = 0;
    for (int it = 0; it < 32; it++) {
        bool more = (it + 1 < 32);
        if (more) FF1_FETCH((it + 1) * 32);

        uint32_t bufb = smu + cur * F1_BUF;
#pragma unroll
        for (int ksb = 0; ksb < 64; ksb += 32) {
            uint32_t bh_[4][2], bl_[4][2];
#pragma unroll
            for (int nb = 0; nb < 2; nb++) {
                uint32_t baddr = bufb + F1_BH +
                    (uint32_t)((wn * 32 + nb * 16 + (lane & 7) + ((lane >> 4) & 1) * 8) * RS +
                               ((lane >> 3) & 1) * 16 + ksb);
                ldmat_x4(bh_[2*nb][0], bh_[2*nb][1], bh_[2*nb+1][0], bh_[2*nb+1][1], baddr);
                ldmat_x4(bl_[2*nb][0], bl_[2*nb][1], bl_[2*nb+1][0], bl_[2*nb+1][1],
                         baddr + (F1_BL - F1_BH));
            }
#pragma unroll
            for (int mf = 0; mf < 2; mf++) {
                uint32_t aaddr = bufb + F1_AH +
                    (uint32_t)((wm * 32 + mf * 16 + (lane & 15)) * RS +
                               (lane >> 4) * 16 + ksb);
                uint32_t ah0, ah1, ah2, ah3, al0, al1, al2, al3;
                ldmat_x4(ah0, ah1, ah2, ah3, aaddr);
                ldmat_x4(al0, al1, al2, al3, aaddr + (F1_AL - F1_AH));
#pragma unroll
                for (int nf = 0; nf < 4; nf++) {
                    mma16816(acc[mf][nf], ah0, ah1, ah2, ah3, bh_[nf][0], bh_[nf][1]);
                    mma16816(acc[mf][nf], ah0, ah1, ah2, ah3, bl_[nf][0], bl_[nf][1]);
                    mma16816(acc[mf][nf], al0, al1, al2, al3, bh_[nf][0], bh_[nf][1]);
                }
            }
        }
        if (more) FF1_STORE(cur ^ 1);
        __syncthreads();
        cur ^= 1;
    }

    // epilogue: bias + relu + split -> g_Ihi/g_Ilo
    const float* bias = f1b + e * NS;
#pragma unroll
    for (int mf = 0; mf < 2; mf++) {
#pragma unroll
        for (int nf = 0; nf < 4; nf++) {
            int c  = wn * 32 + nf * 8 + (lane & 3) * 2;
            float b0 = bias[c], b1 = bias[c + 1];
#pragma unroll
            for (int h = 0; h < 2; h++) {
                int r = wm * 32 + mf * 16 + (lane >> 2) + h * 8;
                float v0 = fmaxf(acc[mf][nf][2*h]     + b0, 0.f);
                float v1 = fmaxf(acc[mf][nf][2*h + 1] + b1, 0.f);
                __nv_bfloat16 h0, l0, h1, l1;
                split_bf16(v0, h0, l0); split_bf16(v1, h1, l1);
                size_t ob = ((size_t)e * NG + gbase + r) * NS + c;
                *(uint32_t*)&g_Ihi[ob] = packbf(h0, h1);
                *(uint32_t*)&g_Ilo[ob] = packbf(l0, l1);
            }
        }
    }
}

// ---------------------------------------------------------------------------
// FF2: D[128g,128d] = I[128,128s] x B2[128,s]^T (3-term), scatter via red.v2.
// 256 threads, warp grid 2x4, warp tile 64x32, BK=32, double-buffered smem.
// ---------------------------------------------------------------------------
#define F2_AH 0
#define F2_AL 10240
#define F2_BH 20480
#define F2_BL 30720
#define F2_BUF 40960
#define F2_WV  (2 * F2_BUF)
#define F2_TOK (F2_WV + 512)
#define F2_SMEM (F2_TOK + 512)

__global__ __launch_bounds__(256) void ff2_mma_kernel(float* __restrict__ out)
{
    extern __shared__ __align__(16) char smc[];
    uint32_t smu = smem_to_u32(smc);
    int tid  = threadIdx.x;
    int lane = tid & 31;
    int wid  = tid >> 5;
    int wm   = wid >> 2;
    int wn   = wid & 3;
    int e     = blockIdx.z;
    int gbase = blockIdx.x * 128;
    int nbase = blockIdx.y * 128;

    float* swv = (float*)(smc + F2_WV);
    int*   stok = (int*)(smc + F2_TOK);
    if (tid < 128) {
        int g = gbase + tid;
        swv[tid]  = g_w[g * NE + e];
        stok[tid] = g * TG + g_sel[g * NE + e];
    }

    // loaders: row = tid/2 (0..127), chunks (tid%2)*2 + {0,1} of 8 bf16
    int r_  = tid >> 1;
    int c0 = (tid & 1) << 1;
    const __nv_bfloat16* ahrow = g_Ihi + ((size_t)e * NG + gbase + r_) * NS;
    const __nv_bfloat16* alrow = g_Ilo + ((size_t)e * NG + gbase + r_) * NS;
    const __nv_bfloat16* bhrow = g_B2hi + ((size_t)e * DD + nbase + r_) * NS;
    const __nv_bfloat16* blrow = g_B2lo + ((size_t)e * DD + nbase + r_) * NS;

    float acc[4][4][4];
#pragma unroll
    for (int i = 0; i < 4; i++)
#pragma unroll
        for (int j = 0; j < 4; j++)
#pragma unroll
            for (int q = 0; q < 4; q++) acc[i][j][q] = 0.f;

    uint4 pah[2], pal[2], pbh[2], pbl[2];

#define FF2_FETCH(kt) do {                                                   \
        pah[0] = *(const uint4*)(ahrow + (kt) + c0 * 8);                     \
        pah[1] = *(const uint4*)(ahrow + (kt) + c0 * 8 + 8);                 \
        pal[0] = *(const uint4*)(alrow + (kt) + c0 * 8);                     \
        pal[1] = *(const uint4*)(alrow + (kt) + c0 * 8 + 8);                 \
        pbh[0] = *(const uint4*)(bhrow + (kt) + c0 * 8);                     \
        pbh[1] = *(const uint4*)(bhrow + (kt) + c0 * 8 + 8);                 \
        pbl[0] = *(const uint4*)(blrow + (kt) + c0 * 8);                     \
        pbl[1] = *(const uint4*)(blrow + (kt) + c0 * 8 + 8);                 \
    } while (0)

#define FF2_STORE(b) do {                                                    \
        char* bb = smc + (b) * F2_BUF;                                       \
        _Pragma("unroll")                                                    \
        for (int j = 0; j < 2; j++) {                                        \
            int off = r_ * RS + (c0 + j) * 16;                               \
            *(uint4*)(bb + F2_AH + off) = pah[j];                            \
            *(uint4*)(bb + F2_AL + off) = pal[j];                            \
            *(uint4*)(bb + F2_BH + off) = pbh[j];                            \
            *(uint4*)(bb + F2_BL + off) = pbl[j];                            \
        }                                                                    \
    } while (0)

    FF2_FETCH(0);
    FF2_STORE(0);
    __syncthreads();

    int cur = 0;
    for (int it = 0; it < 4; it++) {
        bool more = (it + 1 < 4);
        if (more) FF2_FETCH((it + 1) * 32);

        uint32_t bufb = smu + cur * F2_BUF;
#pragma unroll
        for (int ksb = 0; ksb < 64; ksb += 32) {
            uint32_t bh_[4][2], bl_[4][2];
#pragma unroll
            for (int nb = 0; nb < 2; nb++) {
                uint32_t baddr = bufb + F2_BH +
                    (uint32_t)((wn * 32 + nb * 16 + (lane & 7) + ((lane >> 4) & 1) * 8) * RS +
                               ((lane >> 3) & 1) * 16 + ksb);
                ldmat_x4(bh_[2*nb][0], bh_[2*nb][1], bh_[2*nb+1][0], bh_[2*nb+1][1], baddr);
                ldmat_x4(bl_[2*nb][0], bl_[2*nb][1], bl_[2*nb+1][0], bl_[2*nb+1][1],
                         baddr + (F2_BL - F2_BH));
            }
#pragma unroll
            for (int mf = 0; mf < 4; mf++) {
                uint32_t aaddr = bufb + F2_AH +
                    (uint32_t)((wm * 64 + mf * 16 + (lane & 15)) * RS +
                               (lane >> 4) * 16 + ksb);
                uint32_t ah0, ah1, ah2, ah3, al0, al1, al2, al3;
                ldmat_x4(ah0, ah1, ah2, ah3, aaddr);
                ldmat_x4(al0, al1, al2, al3, aaddr + (F2_AL - F2_AH));
#pragma unroll
                for (int nf = 0; nf < 4; nf++) {
                    mma16816(acc[mf][nf], ah0, ah1, ah2, ah3, bh_[nf][0], bh_[nf][1]);
                    mma16816(acc[mf][nf], ah0, ah1, ah2, ah3, bl_[nf][0], bl_[nf][1]);
                    mma16816(acc[mf][nf], al0, al1, al2, al3, bh_[nf][0], bh_[nf][1]);
                }
            }
        }
        if (more) FF2_STORE(cur ^ 1);
        __syncthreads();
        cur ^= 1;
    }

    // epilogue: scale by w, scatter-add to out[token]
#pragma unroll
    for (int mf = 0; mf < 4; mf++) {
#pragma unroll
        for (int nf = 0; nf < 4; nf++) {
            int c = wn * 32 + nf * 8 + (lane & 3) * 2;
#pragma unroll
            for (int h = 0; h < 2; h++) {
                int r = wm * 64 + mf * 16 + (lane >> 2) + h * 8;
                float wv = swv[r];
                float* p = out + (size_t)stok[r] * DD + nbase + c;
                float v0 = wv * acc[mf][nf][2*h];
                float v1 = wv * acc[mf][nf][2*h + 1];
                asm volatile("red.global.add.v2.f32 [%0], {%1, %2};"
                             :: "l"(p), "f"(v0), "f"(v1) : "memory");
            }
        }
    }
}

// ---------------------------------------------------------------------------
extern "C" void kernel_launch(void* const* d_in, const int* in_sizes, int n_in,
                              void* d_out, int out_size) {
    const float* x    = (const float*)d_in[0];
    const float* ctrl = (const float*)d_in[1];
    const float* f1   = (const float*)d_in[2];
    const float* f2   = (const float*)d_in[3];
    const float* f1b  = (const float*)d_in[4];
    float* out = (float*)d_out;

    cudaFuncSetAttribute(ff1_mma_kernel, cudaFuncAttributeMaxDynamicSharedMemorySize, F1_SMEM);
    cudaFuncSetAttribute(ff2_mma_kernel, cudaFuncAttributeMaxDynamicSharedMemorySize, F2_SMEM);

    cudaMemsetAsync(out, 0, (size_t)out_size * sizeof(float), 0);
    router_kernel<<<NG * TG / RT, 256>>>(x, ctrl);
    transpose_f1_kernel<<<dim3(32, 4, 32), dim3(32, 8)>>>(f1);
    transpose_f2_kernel<<<dim3(32, 4, 32), dim3(32, 8)>>>(f2);
    ff1_mma_kernel<<<dim3(8, 32), 256, F1_SMEM>>>(x, f1b);
    ff2_mma_kernel<<<dim3(4, 8, 32), 256, F2_SMEM>>>(out);
}

// round 6
// speedup vs baseline: 1.5938x; 1.0429x over previous
#include <cuda_runtime.h>
#include <cuda_bf16.h>
#include <cstdint>

#define NG 512   // total groups
#define TG 32    // tokens per group
#define DD 1024  // model dim
#define NE 32    // experts
#define NS 128   // expert hidden size

__device__ float g_w[NG * NE];
__device__ int   g_sel[NG * NE];
__device__ float g_Lp[2 * NG * TG * NE];   // split-K partial logits (4 MB)
// pre-transposed + bf16-split weights: B1[e][n][k], B2[e][d][s]
__device__ __nv_bfloat16 g_B1hi[(size_t)NE * NS * DD];
__device__ __nv_bfloat16 g_B1lo[(size_t)NE * NS * DD];
__device__ __nv_bfloat16 g_B2hi[(size_t)NE * DD * NS];
__device__ __nv_bfloat16 g_B2lo[(size_t)NE * DD * NS];
// inner activations, bf16-split: I[e][g][s]
__device__ __nv_bfloat16 g_Ihi[(size_t)NE * NG * NS];
__device__ __nv_bfloat16 g_Ilo[(size_t)NE * NG * NS];

// ============================ helpers ============================
static __device__ __forceinline__ uint32_t smem_to_u32(const void* p) {
    uint32_t a;
    asm("{ .reg .u64 t; cvta.to.shared.u64 t, %1; cvt.u32.u64 %0, t; }"
        : "=r"(a) : "l"(p));
    return a;
}
static __device__ __forceinline__ void ldmat_x4(
    uint32_t& r0, uint32_t& r1, uint32_t& r2, uint32_t& r3, uint32_t addr)
{
    asm volatile("ldmatrix.sync.aligned.m8n8.x4.shared.b16 {%0,%1,%2,%3}, [%4];"
                 : "=r"(r0), "=r"(r1), "=r"(r2), "=r"(r3) : "r"(addr));
}
static __device__ __forceinline__ void mma16816(
    float* d, uint32_t a0, uint32_t a1, uint32_t a2, uint32_t a3,
    uint32_t b0, uint32_t b1)
{
    asm volatile("mma.sync.aligned.m16n8k16.row.col.f32.bf16.bf16.f32 "
                 "{%0,%1,%2,%3}, {%4,%5,%6,%7}, {%8,%9}, {%0,%1,%2,%3};"
                 : "+f"(d[0]), "+f"(d[1]), "+f"(d[2]), "+f"(d[3])
                 : "r"(a0), "r"(a1), "r"(a2), "r"(a3), "r"(b0), "r"(b1));
}
// ---- packed f32x2 helpers (router) ----
static __device__ __forceinline__ unsigned long long pack2(float lo, float hi) {
    unsigned long long r;
    asm("mov.b64 %0, {%1, %2};" : "=l"(r) : "f"(lo), "f"(hi));
    return r;
}
static __device__ __forceinline__ void fma2(unsigned long long &d,
                                            unsigned long long a, unsigned long long b) {
    asm("fma.rn.f32x2 %0, %1, %2, %0;" : "+l"(d) : "l"(a), "l"(b));
}
static __device__ __forceinline__ float2 unpack2(unsigned long long v) {
    float lo, hi;
    asm("mov.b64 {%0, %1}, %2;" : "=f"(lo), "=f"(hi) : "l"(v));
    return make_float2(lo, hi);
}
static __device__ __forceinline__ void split_bf16(float v, __nv_bfloat16& h, __nv_bfloat16& l) {
    h = __float2bfloat16_rn(v);
    l = __float2bfloat16_rn(v - __bfloat162float(h));
}
static __device__ __forceinline__ uint32_t packbf(__nv_bfloat16 a, __nv_bfloat16 b) {
    __nv_bfloat162 p = __halves2bfloat162(a, b);
    return *(uint32_t*)&p;
}

// ---------------------------------------------------------------------------
// Router part: 64 tokens x 32 experts x K-half (512) per CTA. 128 threads,
// 4x4 micro in f32x2. Grid (256, 2). Writes partial logits to g_Lp.
// ---------------------------------------------------------------------------
#define RT 64
#define RDC 64
#define XPAD 68

__global__ __launch_bounds__(128) void router_part_kernel(
    const float* __restrict__ x, const float* __restrict__ ctrl)
{
    __shared__ __align__(16) float xs[RT * XPAD];
    __shared__ __align__(16) float cs[RDC][NE];
    int tid = threadIdx.x;
    int tokbase = blockIdx.x * RT;
    int kbase   = blockIdx.y * (DD / 2);

    int mt = (tid >> 3) << 2;   // token offset 0..60
    int et = (tid & 7) << 2;    // expert offset 0..28

    unsigned long long acc[4][2];
#pragma unroll
    for (int i = 0; i < 4; i++) { acc[i][0] = 0ULL; acc[i][1] = 0ULL; }

    for (int dc = kbase; dc < kbase + DD / 2; dc += RDC) {
        __syncthreads();
        // x chunk: 64 tokens x 64 d
#pragma unroll
        for (int it = 0; it < 8; it++) {
            int t  = (tid >> 4) + (it << 3);
            int d4 = (tid & 15) << 2;
            *(float4*)&xs[t * XPAD + d4] =
                *(const float4*)(x + (size_t)(tokbase + t) * DD + dc + d4);
        }
        // ctrl chunk: 64 d x 32 e
#pragma unroll
        for (int it = 0; it < 4; it++) {
            int q  = tid + (it << 7);
            int d  = q >> 3;
            int e4 = (q & 7) << 2;
            *(float4*)&cs[d][e4] = *(const float4*)(ctrl + (size_t)(dc + d) * NE + e4);
        }
        __syncthreads();
#pragma unroll 4
        for (int d = 0; d < RDC; d += 4) {
            float4 xr[4];
#pragma unroll
            for (int i = 0; i < 4; i++)
                xr[i] = *(const float4*)&xs[(mt + i) * XPAD + d];
#pragma unroll
            for (int dd = 0; dd < 4; dd++) {
                ulonglong2 cb = *(const ulonglong2*)&cs[d + dd][et];
                float xv[4];
                xv[0] = (dd == 0) ? xr[0].x : (dd == 1) ? xr[0].y : (dd == 2) ? xr[0].z : xr[0].w;
                xv[1] = (dd == 0) ? xr[1].x : (dd == 1) ? xr[1].y : (dd == 2) ? xr[1].z : xr[1].w;
                xv[2] = (dd == 0) ? xr[2].x : (dd == 1) ? xr[2].y : (dd == 2) ? xr[2].z : xr[2].w;
                xv[3] = (dd == 0) ? xr[3].x : (dd == 1) ? xr[3].y : (dd == 2) ? xr[3].z : xr[3].w;
#pragma unroll
                for (int i = 0; i < 4; i++) {
                    unsigned long long ad = pack2(xv[i], xv[i]);
                    fma2(acc[i][0], ad, cb.x);
                    fma2(acc[i][1], ad, cb.y);
                }
            }
        }
    }

    float* Lp = g_Lp + (size_t)blockIdx.y * (NG * TG * NE);
#pragma unroll
    for (int i = 0; i < 4; i++) {
        float2 v0 = unpack2(acc[i][0]);
        float2 v1 = unpack2(acc[i][1]);
        *(float4*)&Lp[(size_t)(tokbase + mt + i) * NE + et] =
            make_float4(v0.x, v0.y, v1.x, v1.y);
    }
}

// ---------------------------------------------------------------------------
// Router finalize: per group, sum K-halves + tie-break, argmax + softmax-sum.
// Grid 512 blocks x 32 threads (thread = expert).
// ---------------------------------------------------------------------------
__global__ __launch_bounds__(32) void router_fin_kernel()
{
    int g = blockIdx.x;
    int e = threadIdx.x;
    const float* p0 = g_Lp + (size_t)(g * TG) * NE + e;
    const float* p1 = p0 + (size_t)NG * TG * NE;
    const float step = 1e-6f / 31.0f;

    float L[TG];
    float m = -1e30f;
    int am = 0;
#pragma unroll
    for (int t = 0; t < TG; t++) {
        float v = p0[t * NE] + p1[t * NE] + (float)t * step;
        L[t] = v;
        if (v > m) { m = v; am = t; }
    }
    float s = 0.f;
#pragma unroll
    for (int t = 0; t < TG; t++) s += __expf(L[t] - m);
    g_w[g * NE + e]   = 1.0f / s;
    g_sel[g * NE + e] = am;
}

// ---------------------------------------------------------------------------
// Weight transpose + bf16 split (merged): z<32 -> f1 expert z; else f2.
// f1[k][e][n] -> B1[e][n][k];  f2[e][s][d] -> B2[e][d][s]
// ---------------------------------------------------------------------------
__global__ __launch_bounds__(256) void prep_weights_kernel(
    const float* __restrict__ f1, const float* __restrict__ f2)
{
    __shared__ float tile[32][33];
    int z  = blockIdx.z;
    int tx = threadIdx.x, ty = threadIdx.y;  // 32 x 8
    if (z < 32) {
        int e = z, nt = blockIdx.y, kt = blockIdx.x;
#pragma unroll
        for (int r = 0; r < 4; r++) {
            int k = kt * 32 + ty + r * 8;
            tile[ty + r * 8][tx] = f1[((size_t)k * NE + e) * NS + nt * 32 + tx];
        }
        __syncthreads();
#pragma unroll
        for (int r = 0; r < 4; r++) {
            int n = nt * 32 + ty + r * 8;
            int k = kt * 32 + tx;
            float v = tile[tx][ty + r * 8];
            __nv_bfloat16 h, l;
            split_bf16(v, h, l);
            size_t idx = ((size_t)e * NS + n) * DD + k;
            g_B1hi[idx] = h;
            g_B1lo[idx] = l;
        }
    } else {
        int e = z - 32, st = blockIdx.y, dt = blockIdx.x;
#pragma unroll
        for (int r = 0; r < 4; r++) {
            int s = st * 32 + ty + r * 8;
            tile[ty + r * 8][tx] = f2[((size_t)e * NS + s) * DD + dt * 32 + tx];
        }
        __syncthreads();
#pragma unroll
        for (int r = 0; r < 4; r++) {
            int d = dt * 32 + ty + r * 8;
            int s = st * 32 + tx;
            float v = tile[tx][ty + r * 8];
            __nv_bfloat16 h, l;
            split_bf16(v, h, l);
            size_t idx = ((size_t)e * DD + d) * NS + s;
            g_B2hi[idx] = h;
            g_B2lo[idx] = l;
        }
    }
}

// ---------------------------------------------------------------------------
// FF1: D[64g,128s] = sum_k (w*x[sel])[64,k] x B1[128,k]^T, bf16 3-term split.
// 256 threads, warp grid 2x4, warp tile 32x32, BK=32, double-buffered smem.
// ---------------------------------------------------------------------------
#define RS 80
#define F1_AH 0
#define F1_AL 5120
#define F1_BH 10240
#define F1_BL 20480
#define F1_BUF 30720
#define F1_SMEM (2 * F1_BUF)

__global__ __launch_bounds__(256) void ff1_mma_kernel(
    const float* __restrict__ x, const float* __restrict__ f1b)
{
    extern __shared__ __align__(16) char smc[];
    uint32_t smu = smem_to_u32(smc);
    int tid  = threadIdx.x;
    int lane = tid & 31;
    int wid  = tid >> 5;
    int wm   = wid >> 2;     // 0..1
    int wn   = wid & 3;      // 0..3
    int e     = blockIdx.y;
    int gbase = blockIdx.x * 64;

    int ar  = tid >> 2;
    int ac0 = (tid & 3) << 1;
    int gg  = gbase + ar;
    float wv = g_w[gg * NE + e];
    const float* arow = x + (size_t)(gg * TG + g_sel[gg * NE + e]) * DD;

    int br  = tid >> 1;
    int bc0 = (tid & 1) << 1;
    const __nv_bfloat16* bhrow = g_B1hi + ((size_t)e * NS + br) * DD;
    const __nv_bfloat16* blrow = g_B1lo + ((size_t)e * NS + br) * DD;

    float acc[2][4][4];
#pragma unroll
    for (int i = 0; i < 2; i++)
#pragma unroll
        for (int j = 0; j < 4; j++)
#pragma unroll
            for (int q = 0; q < 4; q++) acc[i][j][q] = 0.f;

    float4 pa[2];
    uint4  pbh[2], pbl[2];

#define FF1_FETCH(kt) do {                                                   \
        pa[0]  = *(const float4*)(arow + (kt) + ac0 * 4);                    \
        pa[1]  = *(const float4*)(arow + (kt) + ac0 * 4 + 4);                \
        pbh[0] = *(const uint4*)(bhrow + (kt) + bc0 * 8);                    \
        pbh[1] = *(const uint4*)(bhrow + (kt) + bc0 * 8 + 8);                \
        pbl[0] = *(const uint4*)(blrow + (kt) + bc0 * 8);                    \
        pbl[1] = *(const uint4*)(blrow + (kt) + bc0 * 8 + 8);                \
    } while (0)

#define FF1_STORE(b) do {                                                    \
        char* bb = smc + (b) * F1_BUF;                                       \
        _Pragma("unroll")                                                    \
        for (int j = 0; j < 2; j++) {                                        \
            float4 v = pa[j];                                                \
            v.x *= wv; v.y *= wv; v.z *= wv; v.w *= wv;                      \
            __nv_bfloat16 h0,l0,h1,l1,h2,l2,h3,l3;                           \
            split_bf16(v.x,h0,l0); split_bf16(v.y,h1,l1);                    \
            split_bf16(v.z,h2,l2); split_bf16(v.w,h3,l3);                    \
            int off = ar * RS + (ac0 + j) * 8;                               \
            *(uint2*)(bb + F1_AH + off) = make_uint2(packbf(h0,h1), packbf(h2,h3)); \
            *(uint2*)(bb + F1_AL + off) = make_uint2(packbf(l0,l1), packbf(l2,l3)); \
        }                                                                    \
        _Pragma("unroll")                                                    \
        for (int j = 0; j < 2; j++) {                                        \
            int off = br * RS + (bc0 + j) * 16;                              \
            *(uint4*)(bb + F1_BH + off) = pbh[j];                            \
            *(uint4*)(bb + F1_BL + off) = pbl[j];                            \
        }                                                                    \
    } while (0)

    FF1_FETCH(0);
    FF1_STORE(0);
    __syncthreads();

    int cur = 0;
    for (int it = 0; it < 32; it++) {
        bool more = (it + 1 < 32);
        if (more) FF1_FETCH((it + 1) * 32);

        uint32_t bufb = smu + cur * F1_BUF;
#pragma unroll
        for (int ksb = 0; ksb < 64; ksb += 32) {
            uint32_t bh_[4][2], bl_[4][2];
#pragma unroll
            for (int nb = 0; nb < 2; nb++) {
                uint32_t baddr = bufb + F1_BH +
                    (uint32_t)((wn * 32 + nb * 16 + (lane & 7) + ((lane >> 4) & 1) * 8) * RS +
                               ((lane >> 3) & 1) * 16 + ksb);
                ldmat_x4(bh_[2*nb][0], bh_[2*nb][1], bh_[2*nb+1][0], bh_[2*nb+1][1], baddr);
                ldmat_x4(bl_[2*nb][0], bl_[2*nb][1], bl_[2*nb+1][0], bl_[2*nb+1][1],
                         baddr + (F1_BL - F1_BH));
            }
#pragma unroll
            for (int mf = 0; mf < 2; mf++) {
                uint32_t aaddr = bufb + F1_AH +
                    (uint32_t)((wm * 32 + mf * 16 + (lane & 15)) * RS +
                               (lane >> 4) * 16 + ksb);
                uint32_t ah0, ah1, ah2, ah3, al0, al1, al2, al3;
                ldmat_x4(ah0, ah1, ah2, ah3, aaddr);
                ldmat_x4(al0, al1, al2, al3, aaddr + (F1_AL - F1_AH));
#pragma unroll
                for (int nf = 0; nf < 4; nf++) {
                    mma16816(acc[mf][nf], ah0, ah1, ah2, ah3, bh_[nf][0], bh_[nf][1]);
                    mma16816(acc[mf][nf], ah0, ah1, ah2, ah3, bl_[nf][0], bl_[nf][1]);
                    mma16816(acc[mf][nf], al0, al1, al2, al3, bh_[nf][0], bh_[nf][1]);
                }
            }
        }
        if (more) FF1_STORE(cur ^ 1);
        __syncthreads();
        cur ^= 1;
    }

    const float* bias = f1b + e * NS;
#pragma unroll
    for (int mf = 0; mf < 2; mf++) {
#pragma unroll
        for (int nf = 0; nf < 4; nf++) {
            int c  = wn * 32 + nf * 8 + (lane & 3) * 2;
            float b0 = bias[c], b1 = bias[c + 1];
#pragma unroll
            for (int h = 0; h < 2; h++) {
                int r = wm * 32 + mf * 16 + (lane >> 2) + h * 8;
                float v0 = fmaxf(acc[mf][nf][2*h]     + b0, 0.f);
                float v1 = fmaxf(acc[mf][nf][2*h + 1] + b1, 0.f);
                __nv_bfloat16 h0, l0, h1, l1;
                split_bf16(v0, h0, l0); split_bf16(v1, h1, l1);
                size_t ob = ((size_t)e * NG + gbase + r) * NS + c;
                *(uint32_t*)&g_Ihi[ob] = packbf(h0, h1);
                *(uint32_t*)&g_Ilo[ob] = packbf(l0, l1);
            }
        }
    }
}

// ---------------------------------------------------------------------------
// FF2: D[128g,128d] = I[128,128s] x B2[128,s]^T (3-term), scatter via red.v2.
// ---------------------------------------------------------------------------
#define F2_AH 0
#define F2_AL 10240
#define F2_BH 20480
#define F2_BL 30720
#define F2_BUF 40960
#define F2_WV  (2 * F2_BUF)
#define F2_TOK (F2_WV + 512)
#define F2_SMEM (F2_TOK + 512)

__global__ __launch_bounds__(256) void ff2_mma_kernel(float* __restrict__ out)
{
    extern __shared__ __align__(16) char smc[];
    uint32_t smu = smem_to_u32(smc);
    int tid  = threadIdx.x;
    int lane = tid & 31;
    int wid  = tid >> 5;
    int wm   = wid >> 2;
    int wn   = wid & 3;
    int e     = blockIdx.z;
    int gbase = blockIdx.x * 128;
    int nbase = blockIdx.y * 128;

    float* swv = (float*)(smc + F2_WV);
    int*   stok = (int*)(smc + F2_TOK);
    if (tid < 128) {
        int g = gbase + tid;
        swv[tid]  = g_w[g * NE + e];
        stok[tid] = g * TG + g_sel[g * NE + e];
    }

    int r_  = tid >> 1;
    int c0 = (tid & 1) << 1;
    const __nv_bfloat16* ahrow = g_Ihi + ((size_t)e * NG + gbase + r_) * NS;
    const __nv_bfloat16* alrow = g_Ilo + ((size_t)e * NG + gbase + r_) * NS;
    const __nv_bfloat16* bhrow = g_B2hi + ((size_t)e * DD + nbase + r_) * NS;
    const __nv_bfloat16* blrow = g_B2lo + ((size_t)e * DD + nbase + r_) * NS;

    float acc[4][4][4];
#pragma unroll
    for (int i = 0; i < 4; i++)
#pragma unroll
        for (int j = 0; j < 4; j++)
#pragma unroll
            for (int q = 0; q < 4; q++) acc[i][j][q] = 0.f;

    uint4 pah[2], pal[2], pbh[2], pbl[2];

#define FF2_FETCH(kt) do {                                                   \
        pah[0] = *(const uint4*)(ahrow + (kt) + c0 * 8);                     \
        pah[1] = *(const uint4*)(ahrow + (kt) + c0 * 8 + 8);                 \
        pal[0] = *(const uint4*)(alrow + (kt) + c0 * 8);                     \
        pal[1] = *(const uint4*)(alrow + (kt) + c0 * 8 + 8);                 \
        pbh[0] = *(const uint4*)(bhrow + (kt) + c0 * 8);                     \
        pbh[1] = *(const uint4*)(bhrow + (kt) + c0 * 8 + 8);                 \
        pbl[0] = *(const uint4*)(blrow + (kt) + c0 * 8);                     \
        pbl[1] = *(const uint4*)(blrow + (kt) + c0 * 8 + 8);                 \
    } while (0)

#define FF2_STORE(b) do {                                                    \
        char* bb = smc + (b) * F2_BUF;                                       \
        _Pragma("unroll")                                                    \
        for (int j = 0; j < 2; j++) {                                        \
            int off = r_ * RS + (c0 + j) * 16;                               \
            *(uint4*)(bb + F2_AH + off) = pah[j];                            \
            *(uint4*)(bb + F2_AL + off) = pal[j];                            \
            *(uint4*)(bb + F2_BH + off) = pbh[j];                            \
            *(uint4*)(bb + F2_BL + off) = pbl[j];                            \
        }                                                                    \
    } while (0)

    FF2_FETCH(0);
    FF2_STORE(0);
    __syncthreads();

    int cur = 0;
    for (int it = 0; it < 4; it++) {
        bool more = (it + 1 < 4);
        if (more) FF2_FETCH((it + 1) * 32);

        uint32_t bufb = smu + cur * F2_BUF;
#pragma unroll
        for (int ksb = 0; ksb < 64; ksb += 32) {
            uint32_t bh_[4][2], bl_[4][2];
#pragma unroll
            for (int nb = 0; nb < 2; nb++) {
                uint32_t baddr = bufb + F2_BH +
                    (uint32_t)((wn * 32 + nb * 16 + (lane & 7) + ((lane >> 4) & 1) * 8) * RS +
                               ((lane >> 3) & 1) * 16 + ksb);
                ldmat_x4(bh_[2*nb][0], bh_[2*nb][1], bh_[2*nb+1][0], bh_[2*nb+1][1], baddr);
                ldmat_x4(bl_[2*nb][0], bl_[2*nb][1], bl_[2*nb+1][0], bl_[2*nb+1][1],
                         baddr + (F2_BL - F2_BH));
            }
#pragma unroll
            for (int mf = 0; mf < 4; mf++) {
                uint32_t aaddr = bufb + F2_AH +
                    (uint32_t)((wm * 64 + mf * 16 + (lane & 15)) * RS +
                               (lane >> 4) * 16 + ksb);
                uint32_t ah0, ah1, ah2, ah3, al0, al1, al2, al3;
                ldmat_x4(ah0, ah1, ah2, ah3, aaddr);
                ldmat_x4(al0, al1, al2, al3, aaddr + (F2_AL - F2_AH));
#pragma unroll
                for (int nf = 0; nf < 4; nf++) {
                    mma16816(acc[mf][nf], ah0, ah1, ah2, ah3, bh_[nf][0], bh_[nf][1]);
                    mma16816(acc[mf][nf], ah0, ah1, ah2, ah3, bl_[nf][0], bl_[nf][1]);
                    mma16816(acc[mf][nf], al0, al1, al2, al3, bh_[nf][0], bh_[nf][1]);
                }
            }
        }
        if (more) FF2_STORE(cur ^ 1);
        __syncthreads();
        cur ^= 1;
    }

#pragma unroll
    for (int mf = 0; mf < 4; mf++) {
#pragma unroll
        for (int nf = 0; nf < 4; nf++) {
            int c = wn * 32 + nf * 8 + (lane & 3) * 2;
#pragma unroll
            for (int h = 0; h < 2; h++) {
                int r = wm * 64 + mf * 16 + (lane >> 2) + h * 8;
                float wv = swv[r];
                float* p = out + (size_t)stok[r] * DD + nbase + c;
                float v0 = wv * acc[mf][nf][2*h];
                float v1 = wv * acc[mf][nf][2*h + 1];
                asm volatile("red.global.add.v2.f32 [%0], {%1, %2};"
                             :: "l"(p), "f"(v0), "f"(v1) : "memory");
            }
        }
    }
}

// ---------------------------------------------------------------------------
extern "C" void kernel_launch(void* const* d_in, const int* in_sizes, int n_in,
                              void* d_out, int out_size) {
    const float* x    = (const float*)d_in[0];
    const float* ctrl = (const float*)d_in[1];
    const float* f1   = (const float*)d_in[2];
    const float* f2   = (const float*)d_in[3];
    const float* f1b  = (const float*)d_in[4];
    float* out = (float*)d_out;

    cudaFuncSetAttribute(ff1_mma_kernel, cudaFuncAttributeMaxDynamicSharedMemorySize, F1_SMEM);
    cudaFuncSetAttribute(ff2_mma_kernel, cudaFuncAttributeMaxDynamicSharedMemorySize, F2_SMEM);

    cudaMemsetAsync(out, 0, (size_t)out_size * sizeof(float), 0);
    router_part_kernel<<<dim3(NG * TG / RT, 2), 128>>>(x, ctrl);
    prep_weights_kernel<<<dim3(32, 4, 64), dim3(32, 8)>>>(f1, f2);
    router_fin_kernel<<<NG, 32>>>();
    ff1_mma_kernel<<<dim3(8, 32), 256, F1_SMEM>>>(x, f1b);
    ff2_mma_kernel<<<dim3(4, 8, 32), 256, F2_SMEM>>>(out);
}